// round 13
// baseline (speedup 1.0000x reference)
#include <cuda_runtime.h>
#include <cuda_bf16.h>
#include <cstdint>

#define BB   2
#define LL   4096
#define DM   1024
#define HH   16
#define DH   64
#define CC   64
#define NCH  64
#define BH   (BB*HH)
#define BL   (BB*LL)
#define NMAT (BB*HH*NCH)
#define MATSZ (DH*DH)
#define P65  65

// ---------------- static device scratch (no allocations) ----------------
__device__ float g_kpre[BL*DM];
__device__ float g_qpre[BL*DM];
__device__ float g_vpre[BL*DM];
__device__ float g_k[NMAT*MATSZ];
__device__ float g_q[NMAT*MATSZ];
__device__ float g_v[NMAT*MATSZ];
__device__ float g_gg[BH*LL];
__device__ float g_bt[BH*LL];
__device__ float g_E[NMAT];
__device__ float g_Lkk[NMAT*MATSZ];
__device__ float g_Lkv[NMAT*MATSZ];
__device__ float g_Ckk[NMAT*MATSZ];
__device__ float g_Ckv[NMAT*MATSZ];
__device__ float g_O[NMAT*MATSZ];
__device__ __nv_bfloat16 g_xhi[BL*DM];
__device__ __nv_bfloat16 g_xlo[BL*DM];
__device__ __nv_bfloat16 g_wh[4][DM*DM];
__device__ __nv_bfloat16 g_wl[4][DM*DM];

// ---------------- helpers ----------------
__device__ __forceinline__ uint32_t smem_u32(const void* p) {
    uint32_t a;
    asm("{ .reg .u64 t; cvta.to.shared.u64 t, %1; cvt.u32.u64 %0, t; }" : "=r"(a) : "l"(p));
    return a;
}
__device__ __forceinline__ void ldsm4(uint32_t* r, uint32_t addr) {
    asm volatile("ldmatrix.sync.aligned.m8n8.x4.shared.b16 {%0,%1,%2,%3}, [%4];"
                 : "=r"(r[0]), "=r"(r[1]), "=r"(r[2]), "=r"(r[3]) : "r"(addr));
}
__device__ __forceinline__ void mma_bf16(float* c, const uint32_t* a, const uint32_t* b) {
    asm volatile(
        "mma.sync.aligned.m16n8k16.row.col.f32.bf16.bf16.f32 "
        "{%0,%1,%2,%3}, {%4,%5,%6,%7}, {%8,%9}, {%0,%1,%2,%3};"
        : "+f"(c[0]), "+f"(c[1]), "+f"(c[2]), "+f"(c[3])
        : "r"(a[0]), "r"(a[1]), "r"(a[2]), "r"(a[3]), "r"(b[0]), "r"(b[1]));
}
__device__ __forceinline__ void cp16(uint32_t dst, const void* src) {
    asm volatile("cp.async.cg.shared.global [%0], [%1], 16;" :: "r"(dst), "l"(src) : "memory");
}
#define CP_COMMIT() asm volatile("cp.async.commit_group;" ::: "memory")
#define CP_WAIT(n)  asm volatile("cp.async.wait_group %0;" :: "n"(n) : "memory")

// SMEM stage: Ahi 0, Alo 10240, Bhi 20480, Blo 30720; stride 40960; 2 stages
#define STG 40960
#define GEMM_SMEM (2*STG)

// ---------------- split x (fp32 -> bf16 hi/lo) ----------------
__global__ __launch_bounds__(256) void split_x(const float* __restrict__ src)
{
    int i = blockIdx.x * 256 + threadIdx.x;
    for (; i < BL * DM / 4; i += gridDim.x * 256) {
        float4 a = *(const float4*)(src + (size_t)i * 4);
        __nv_bfloat16 h0 = __float2bfloat16(a.x), h1 = __float2bfloat16(a.y);
        __nv_bfloat16 h2 = __float2bfloat16(a.z), h3 = __float2bfloat16(a.w);
        __nv_bfloat16 l0 = __float2bfloat16(a.x - __bfloat162float(h0));
        __nv_bfloat16 l1 = __float2bfloat16(a.y - __bfloat162float(h1));
        __nv_bfloat16 l2 = __float2bfloat16(a.z - __bfloat162float(h2));
        __nv_bfloat16 l3 = __float2bfloat16(a.w - __bfloat162float(h3));
        __nv_bfloat162 ph0(h0, h1), ph1(h2, h3), pl0(l0, l1), pl1(l2, l3);
        *(uint2*)(g_xhi + (size_t)i * 4) = make_uint2(*(uint32_t*)&ph0, *(uint32_t*)&ph1);
        *(uint2*)(g_xlo + (size_t)i * 4) = make_uint2(*(uint32_t*)&pl0, *(uint32_t*)&pl1);
    }
}

// ---------------- W (fp32 [k][n]) -> transposed bf16 hi/lo [n][k], fused ----
__global__ __launch_bounds__(256) void wtsplit(
    const float* __restrict__ W0, const float* __restrict__ W1,
    const float* __restrict__ W2, const float* __restrict__ W3)
{
    __shared__ float s[32][33];
    int widx = blockIdx.z;
    const float* W = (widx == 0) ? W0 : (widx == 1) ? W1 : (widx == 2) ? W2 : W3;
    int bk = blockIdx.y << 5, bn = blockIdx.x << 5;
    int lx = threadIdx.x & 31, ly = threadIdx.x >> 5;
#pragma unroll
    for (int i = 0; i < 4; i++) {
        int r = ly + (i << 3);
        s[r][lx] = W[(size_t)(bk + r) * DM + bn + lx];
    }
    __syncthreads();
#pragma unroll
    for (int i = 0; i < 4; i++) {
        int r = ly + (i << 3);
        float v = s[lx][r];
        __nv_bfloat16 h = __float2bfloat16(v);
        __nv_bfloat16 l = __float2bfloat16(v - __bfloat162float(h));
        size_t o = (size_t)(bn + r) * DM + bk + lx;
        g_wh[widx][o] = h;
        g_wl[widx][o] = l;
    }
}

// ---------------- bf16x3 HMMA GEMM (2-stage cp.async, 2 CTAs/SM) ----------
__device__ __forceinline__ void gemm_load_stage(
    uint32_t st, int nbase, int bm, int bn, int k0, int tid)
{
    const __nv_bfloat16* Bh = (const __nv_bfloat16*)g_wh + (size_t)nbase * DM;
    const __nv_bfloat16* Bl = (const __nv_bfloat16*)g_wl + (size_t)nbase * DM;
#pragma unroll
    for (int i = 0; i < 2; i++) {
        int c = tid + (i << 8);
        int row = c >> 2, seg = c & 3;
        uint32_t dst = st + row * 80 + seg * 16;
        size_t ka = (size_t)(bm + row) * DM + k0 + seg * 8;
        size_t kb = (size_t)(bn + row) * DM + k0 + seg * 8;
        cp16(dst,         g_xhi + ka);
        cp16(dst + 10240, g_xlo + ka);
        cp16(dst + 20480, Bh + kb);
        cp16(dst + 30720, Bl + kb);
    }
}

__global__ __launch_bounds__(256, 2) void gemm_mma(
    int nbase, const float* __restrict__ b0, const float* __restrict__ b1,
    const float* __restrict__ b2, float* __restrict__ Cext, int mode)
{
    extern __shared__ char smem[];
    uint32_t sb = smem_u32(smem);

    int tid = threadIdx.x;
    int bn = blockIdx.x << 7, bm = blockIdx.y << 7;
    int wid = tid >> 5, l = tid & 31;
    int wm = (wid & 3) << 5;
    int wn = (wid >> 2) << 6;

    int region = bn >> 10;
    const float* bias = mode ? b0 : (region == 0 ? b0 : region == 1 ? b1 : b2);
    float* C = mode ? Cext : (region == 0 ? g_kpre : region == 1 ? g_qpre : g_vpre);
    int bnl = mode ? bn : (bn & 1023);

    uint32_t a_off = (uint32_t)((wm + (l & 15)) * 80 + ((l >> 4) << 4));
    uint32_t b_off = (uint32_t)((wn + ((l >> 4) << 3) + (l & 7)) * 80 + (((l >> 3) & 1) << 4));

    float acc[2][8][4];
#pragma unroll
    for (int mf = 0; mf < 2; mf++)
#pragma unroll
        for (int nf = 0; nf < 8; nf++)
#pragma unroll
            for (int i = 0; i < 4; i++) acc[mf][nf][i] = 0.f;

    gemm_load_stage(sb, nbase, bm, bn, 0, tid); CP_COMMIT();

    const int NK = DM / 32;
    for (int kt = 0; kt < NK; kt++) {
        if (kt + 1 < NK) {
            gemm_load_stage(sb + ((kt + 1) & 1) * STG, nbase, bm, bn, (kt + 1) << 5, tid);
            CP_COMMIT();
            CP_WAIT(1);
        } else {
            CP_WAIT(0);
        }
        __syncthreads();

        uint32_t sA = sb + (kt & 1) * STG;
        uint32_t sAl = sA + 10240, sBh = sA + 20480, sBl = sA + 30720;
#pragma unroll
        for (int ks = 0; ks < 2; ks++) {
            uint32_t koff = ks << 5;
            uint32_t ah[2][4], al[2][4], b[8][2];
#pragma unroll
            for (int mf = 0; mf < 2; mf++) {
                ldsm4(ah[mf], sA  + a_off + mf * (16 * 80) + koff);
                ldsm4(al[mf], sAl + a_off + mf * (16 * 80) + koff);
            }
#pragma unroll
            for (int g = 0; g < 4; g++) {
                uint32_t r[4];
                ldsm4(r, sBh + b_off + g * (16 * 80) + koff);
                b[2 * g][0] = r[0]; b[2 * g][1] = r[1];
                b[2 * g + 1][0] = r[2]; b[2 * g + 1][1] = r[3];
            }
#pragma unroll
            for (int mf = 0; mf < 2; mf++)
#pragma unroll
                for (int nf = 0; nf < 8; nf++) mma_bf16(acc[mf][nf], ah[mf], b[nf]);
#pragma unroll
            for (int mf = 0; mf < 2; mf++)
#pragma unroll
                for (int nf = 0; nf < 8; nf++) mma_bf16(acc[mf][nf], al[mf], b[nf]);
#pragma unroll
            for (int g = 0; g < 4; g++) {
                uint32_t r[4];
                ldsm4(r, sBl + b_off + g * (16 * 80) + koff);
                b[2 * g][0] = r[0]; b[2 * g][1] = r[1];
                b[2 * g + 1][0] = r[2]; b[2 * g + 1][1] = r[3];
            }
#pragma unroll
            for (int mf = 0; mf < 2; mf++)
#pragma unroll
                for (int nf = 0; nf < 8; nf++) mma_bf16(acc[mf][nf], ah[mf], b[nf]);
        }
        __syncthreads();
    }

    int r4 = l >> 2, c2 = (l & 3) << 1;
#pragma unroll
    for (int mf = 0; mf < 2; mf++) {
        int row0 = bm + wm + mf * 16 + r4;
#pragma unroll
        for (int nf = 0; nf < 8; nf++) {
            int col = bnl + wn + nf * 8 + c2;
            float bb0 = bias[col], bb1 = bias[col + 1];
            float2 v0 = make_float2(acc[mf][nf][0] + bb0, acc[mf][nf][1] + bb1);
            float2 v1 = make_float2(acc[mf][nf][2] + bb0, acc[mf][nf][3] + bb1);
            *(float2*)(C + (size_t)row0 * DM + col) = v0;
            *(float2*)(C + (size_t)(row0 + 8) * DM + col) = v1;
        }
    }
}

// ---------------- g / beta projections + activations ----------------
__global__ __launch_bounds__(128) void ab_kernel(
    const float* __restrict__ x, const float* __restrict__ Wa,
    const float* __restrict__ ba, const float* __restrict__ Wb,
    const float* __restrict__ bb, const float* __restrict__ A_log,
    const float* __restrict__ dtb)
{
    __shared__ __align__(16) float xr[DM];
    __shared__ float red[128];
    int bid = blockIdx.x;
    int b = bid >> 12, l = bid & 4095;
    const float4* xs = (const float4*)(x + (size_t)bid * DM);
    float4* xr4 = (float4*)xr;
    xr4[threadIdx.x] = xs[threadIdx.x];
    xr4[threadIdx.x + 128] = xs[threadIdx.x + 128];
    __syncthreads();

    int col = threadIdx.x & 31;
    int seg = threadIdx.x >> 5;
    const float* W = (col < 16) ? (Wa + col) : (Wb + (col - 16));
    float acc = 0.f;
    int k0 = seg << 8;
#pragma unroll 8
    for (int k = 0; k < 256; k++) acc += xr[k0 + k] * W[(size_t)(k0 + k) * HH];
    red[threadIdx.x] = acc;
    __syncthreads();
    if (threadIdx.x < 32) {
        float a = red[threadIdx.x] + red[threadIdx.x + 32] +
                  red[threadIdx.x + 64] + red[threadIdx.x + 96];
        if (col < 16) {
            int h = col;
            float z = a + ba[h] + dtb[h];
            float sp = (z > 20.f) ? z : log1pf(expf(z));
            g_gg[(size_t)(b * HH + h) * LL + l] = -expf(A_log[h]) * sp;
        } else {
            int h = col - 16;
            float z = a + bb[h];
            g_bt[(size_t)(b * HH + h) * LL + l] = 1.f / (1.f + expf(-z));
        }
    }
}

// ---------------- causal depthwise conv(K=4) + silu (+ head L2 norm), fused
__global__ __launch_bounds__(128) void conv_silu_kernel(
    const float* __restrict__ cwk, const float* __restrict__ cbk,
    const float* __restrict__ cwq, const float* __restrict__ cbq,
    const float* __restrict__ cwv, const float* __restrict__ cbv)
{
    int which = blockIdx.z;
    const float* pre = (which == 0) ? g_kpre : (which == 1) ? g_qpre : g_vpre;
    float* out = (which == 0) ? g_k : (which == 1) ? g_q : g_v;
    const float* cw = (which == 0) ? cwk : (which == 1) ? cwq : cwv;
    const float* cb = (which == 0) ? cbk : (which == 1) ? cbq : cbv;
    int do_norm = (which < 2);

    int gwarp = blockIdx.x * 4 + (threadIdx.x >> 5);
    int lane = threadIdx.x & 31;
    int h = gwarp & 15;
    int l = (gwarp >> 4) & 4095;
    int b = gwarp >> 16;
    int d0 = lane, d1 = lane + 32;
    int dm0 = h * DH + d0, dm1 = h * DH + d1;

    float a0 = cb[dm0], a1 = cb[dm1];
    const float* w0 = cw + dm0 * 4;
    const float* w1 = cw + dm1 * 4;
    size_t base = (size_t)b * LL * DM;
#pragma unroll
    for (int i = 0; i < 4; i++) {
        int li = l - 3 + i;
        if (li >= 0) {
            a0 += w0[i] * pre[base + (size_t)li * DM + dm0];
            a1 += w1[i] * pre[base + (size_t)li * DM + dm1];
        }
    }
    float s0 = a0 / (1.f + expf(-a0));
    float s1 = a1 / (1.f + expf(-a1));
    if (do_norm) {
        float ss = s0 * s0 + s1 * s1;
#pragma unroll
        for (int o = 16; o > 0; o >>= 1) ss += __shfl_xor_sync(0xffffffffu, ss, o);
        float sc = 1.f / (sqrtf(ss) + 1e-6f);
        s0 *= sc; s1 *= sc;
    }
    int n = l >> 6, t = l & 63;
    size_t ob = ((size_t)(b * HH + h) * NCH + n) * (CC * DH) + (size_t)t * DH;
    out[ob + d0] = s0;
    out[ob + d1] = s1;
}

// ---------------- Phase A: per-chunk decayed local sums ----------------
__global__ __launch_bounds__(64) void phaseA_kernel()
{
    __shared__ float ks[4096], vs[4096];
    __shared__ float gs[64], bs[64], cs[64], wgt[64];
    int bid = blockIdx.x, t = threadIdx.x;
    size_t base = (size_t)bid * MATSZ;
    for (int i = t; i < 4096; i += 64) { ks[i] = g_k[base + i]; vs[i] = g_v[base + i]; }
    int bh = bid >> 6, n = bid & 63;
    gs[t] = g_gg[(size_t)bh * LL + n * 64 + t];
    bs[t] = g_bt[(size_t)bh * LL + n * 64 + t];
    __syncthreads();
    float c = 0.f;
    for (int j = 0; j <= t; j++) c += gs[j];
    cs[t] = c;
    __syncthreads();
    float cl = cs[63];
    wgt[t] = expf(cl - cs[t]) * bs[t];
    if (t == 0) g_E[bid] = expf(cl);
    __syncthreads();

    float akk[64], akv[64];
#pragma unroll
    for (int d = 0; d < 64; d++) { akk[d] = 0.f; akv[d] = 0.f; }
    for (int m = 0; m < 64; m++) {
        float w = wgt[m];
        float ce = w * ks[m * 64 + t];
        float cv = w * vs[m * 64 + t];
#pragma unroll
        for (int d = 0; d < 64; d++) {
            float kmd = ks[m * 64 + d];
            akk[d] += ce * kmd;
            akv[d] += cv * kmd;
        }
    }
#pragma unroll
    for (int d = 0; d < 64; d++) {
        g_Lkk[base + d * 64 + t] = akk[d];
        g_Lkv[base + d * 64 + t] = akv[d];
    }
}

// ---------------- Scan: carry matrices across chunks (parallel over elems) --
__global__ __launch_bounds__(256) void scan_kernel()
{
    int bh = blockIdx.x;
    int e = blockIdx.y * 256 + threadIdx.x;
    float ckk = ((e >> 6) == (e & 63)) ? 1.f : 0.f;
    float ckv = 0.f;
    const float* EE = g_E + bh * 64;
    size_t base = (size_t)bh * 64 * MATSZ + e;
    for (int n = 0; n < 64; n++) {
        size_t o = base + (size_t)n * MATSZ;
        float E = EE[n];
        g_Ckk[o] = ckk;
        g_Ckv[o] = ckv;
        ckk = E * ckk + g_Lkk[o];
        ckv = E * ckv + g_Lkv[o];
    }
}

// ---------------- Phase C: 128-thread, 2 threads/column ----------
__global__ __launch_bounds__(128) void phaseC_kernel()
{
    __shared__ float shK[64 * P65];
    __shared__ float shQ[64 * P65];
    __shared__ float shV[64 * P65];
    __shared__ float gs[64], bs[64];
    __shared__ float ush2[128], qsh2[128], psh[128], dsh2[128], osh2[128];
    __shared__ float rsh[64], qss[64];

    int tile = blockIdx.x, tid = threadIdx.x;
    int t = tid & 63, h = tid >> 6;
    int r0 = h << 5;
    int bh = tile >> 6, n = tile & 63;
    size_t tb = (size_t)tile * MATSZ;

    float Mreg[32], Sreg[32], Vreg[32];
#pragma unroll
    for (int i = 0; i < 32; i++) {
        Sreg[i] = g_Ckk[tb + (r0 + i) * 64 + t];
        Vreg[i] = g_Ckv[tb + (r0 + i) * 64 + t];
        shK[(r0 + i) * P65 + t] = g_k[tb + (r0 + i) * 64 + t];
        shQ[(r0 + i) * P65 + t] = g_q[tb + (r0 + i) * 64 + t];
        shV[(r0 + i) * P65 + t] = g_v[tb + (r0 + i) * 64 + t];
        Mreg[i] = 0.f;
    }
    if (h == 0) {
        gs[t] = g_gg[(size_t)bh * LL + n * 64 + t];
        bs[t] = g_bt[(size_t)bh * LL + n * 64 + t];
    }
    __syncthreads();

    for (int j = 0; j < 64; j++) {
        float aj = expf(gs[j]);
        float bj = bs[j];
        float kt = shK[j * P65 + t];
        float qjt = shQ[j * P65 + t];
        float vt = shV[j * P65 + t];
        bool refresh = ((j & 31) == 0);

        if (!refresh) {
            float u = 0.f;
#pragma unroll
            for (int i = 0; i < 32; i++) u += Mreg[i] * shK[j * P65 + r0 + i];
            ush2[tid] = u;
            __syncthreads();
            float ku = 0.f, ku2 = 0.f;
#pragma unroll
            for (int i = 0; i < 32; i++) {
                ku  += shK[j * P65 + i]      * (ush2[i]      + ush2[64 + i]);
                ku2 += shK[j * P65 + 32 + i] * (ush2[32 + i] + ush2[96 + i]);
            }
            ku += ku2;
            float ut = ush2[t] + ush2[64 + t];
            float inva = 1.f / aj;
            float cu = (bj / (aj + bj * ku)) * inva * ut;
#pragma unroll
            for (int i = 0; i < 32; i++)
                Mreg[i] = inva * Mreg[i] - cu * (ush2[r0 + i] + ush2[64 + r0 + i]);
        }

        float bk = bj * kt, bv = bj * vt;
#pragma unroll
        for (int i = 0; i < 32; i++) {
            float ki = shK[j * P65 + r0 + i];
            Sreg[i] = aj * Sreg[i] + bk * ki;
            Vreg[i] = aj * Vreg[i] + bv * ki;
        }

        if (refresh) {
            __syncthreads();
#pragma unroll
            for (int i = 0; i < 32; i++) {
                shK[(r0 + i) * P65 + t] = Sreg[i];
                shQ[(r0 + i) * P65 + t] = ((r0 + i) == t) ? 1.f : 0.f;
            }
            __syncthreads();
            for (int p = 0; p < 64; p++) {
                // pivot value is stable since last sync; scale row p
                if (t == p) {
                    float inv = 1.f / shK[p * P65 + p];
#pragma unroll
                    for (int c = 0; c < 32; c++) {
                        shK[p * P65 + r0 + c] *= inv;
                        shQ[p * P65 + r0 + c] *= inv;
                    }
                }
                __syncthreads();
                if (t != p) {
                    float f = shK[t * P65 + p];
#pragma unroll
                    for (int c = 0; c < 32; c++) {
                        shK[t * P65 + r0 + c] -= f * shK[p * P65 + r0 + c];
                        shQ[t * P65 + r0 + c] -= f * shQ[p * P65 + r0 + c];
                    }
                }
                __syncthreads();
            }
#pragma unroll
            for (int i = 0; i < 32; i++) Mreg[i] = shQ[(r0 + i) * P65 + t];
            __syncthreads();
#pragma unroll
            for (int i = 0; i < 32; i++) {
                shK[(r0 + i) * P65 + t] = g_k[tb + (r0 + i) * 64 + t];
                shQ[(r0 + i) * P65 + t] = g_q[tb + (r0 + i) * 64 + t];
            }
            __syncthreads();
        }

        // solve + one refinement
        float qt = 0.f;
#pragma unroll
        for (int i = 0; i < 32; i++) qt += Mreg[i] * shQ[j * P65 + r0 + i];
        qsh2[tid] = qt;
        __syncthreads();
        float rp = 0.f;
#pragma unroll
        for (int i = 0; i < 32; i++) rp += Sreg[i] * (qsh2[r0 + i] + qsh2[64 + r0 + i]);
        psh[tid] = rp;
        __syncthreads();
        if (h == 0) rsh[t] = qjt - (psh[t] + psh[64 + t]);
        __syncthreads();
        float dp = 0.f;
#pragma unroll
        for (int i = 0; i < 32; i++) dp += Mreg[i] * rsh[r0 + i];
        dsh2[tid] = dp;
        __syncthreads();
        if (h == 0) qss[t] = (qsh2[t] + qsh2[64 + t]) + dsh2[t] + dsh2[64 + t];
        __syncthreads();
        float op = 0.f;
#pragma unroll
        for (int i = 0; i < 32; i++) op += qss[r0 + i] * Vreg[i];
        osh2[tid] = op;
        __syncthreads();
        if (h == 0) g_O[tb + j * 64 + t] = osh2[t] + osh2[64 + t];
        __syncthreads();
    }
}

// ---------------- rmsnorm + repack + bf16 hi/lo split (fused) ------------
__global__ __launch_bounds__(128) void rms_split_kernel(const float* __restrict__ nw)
{
    int gwarp = blockIdx.x * 4 + (threadIdx.x >> 5);
    int lane = threadIdx.x & 31;
    int h = gwarp & 15;
    int l = (gwarp >> 4) & 4095;
    int b = gwarp >> 16;
    int n = l >> 6, c = l & 63;
    size_t rb = (((size_t)(b * HH + h) * NCH + n) * CC + c) * DH;
    float o0 = g_O[rb + lane], o1 = g_O[rb + lane + 32];
    float ss = o0 * o0 + o1 * o1;
#pragma unroll
    for (int o = 16; o > 0; o >>= 1) ss += __shfl_xor_sync(0xffffffffu, ss, o);
    float sc = rsqrtf(ss * (1.f / 64.f) + 1e-6f);
    float v0 = o0 * sc * nw[lane];
    float v1 = o1 * sc * nw[lane + 32];
    size_t ob = (size_t)(b * LL + l) * DM + h * DH;
    __nv_bfloat16 h0 = __float2bfloat16(v0);
    __nv_bfloat16 h1 = __float2bfloat16(v1);
    g_xhi[ob + lane] = h0;
    g_xhi[ob + lane + 32] = h1;
    g_xlo[ob + lane] = __float2bfloat16(v0 - __bfloat162float(h0));
    g_xlo[ob + lane + 32] = __float2bfloat16(v1 - __bfloat162float(h1));
}

extern "C" void kernel_launch(void* const* d_in, const int* in_sizes, int n_in,
                              void* d_out, int out_size)
{
    const float* x   = (const float*)d_in[0];
    const float* Wk  = (const float*)d_in[1];  const float* bk  = (const float*)d_in[2];
    const float* Wq  = (const float*)d_in[3];  const float* bq  = (const float*)d_in[4];
    const float* Wv  = (const float*)d_in[5];  const float* bv  = (const float*)d_in[6];
    const float* Wa  = (const float*)d_in[7];  const float* ba  = (const float*)d_in[8];
    const float* Wbt = (const float*)d_in[9];  const float* bbt = (const float*)d_in[10];
    const float* Wo  = (const float*)d_in[11]; const float* bo  = (const float*)d_in[12];
    const float* A_log = (const float*)d_in[13];
    const float* dtb = (const float*)d_in[14];
    const float* cwk = (const float*)d_in[15]; const float* cbk = (const float*)d_in[16];
    const float* cwq = (const float*)d_in[17]; const float* cbq = (const float*)d_in[18];
    const float* cwv = (const float*)d_in[19]; const float* cbv = (const float*)d_in[20];
    const float* nw  = (const float*)d_in[21];
    float* out = (float*)d_out;

    cudaFuncSetAttribute(gemm_mma, cudaFuncAttributeMaxDynamicSharedMemorySize, GEMM_SMEM);

    wtsplit<<<dim3(32, 32, 4), 256>>>(Wk, Wq, Wv, Wo);
    split_x<<<4096, 256>>>(x);
    ab_kernel<<<BL, 128>>>(x, Wa, ba, Wbt, bbt, A_log, dtb);
    gemm_mma<<<dim3(3 * DM / 128, BL / 128), 256, GEMM_SMEM>>>(0, bk, bq, bv, nullptr, 0);
    conv_silu_kernel<<<dim3(BB * LL * HH / 4, 1, 3), 128>>>(cwk, cbk, cwq, cbq, cwv, cbv);
    phaseA_kernel<<<NMAT, 64>>>();
    scan_kernel<<<dim3(BH, 16), 256>>>();
    phaseC_kernel<<<NMAT, 128>>>();
    rms_split_kernel<<<BB * LL * HH / 4, 128>>>(nw);
    gemm_mma<<<dim3(DM / 128, BL / 128), 256, GEMM_SMEM>>>(3 * DM, bo, nullptr, nullptr, out, 1);
}

// round 15
// speedup vs baseline: 1.1880x; 1.1880x over previous
#include <cuda_runtime.h>
#include <cuda_bf16.h>
#include <cstdint>

#define BB   2
#define LL   4096
#define DM   1024
#define HH   16
#define DH   64
#define CC   64
#define NCH  64
#define BH   (BB*HH)
#define BL   (BB*LL)
#define NMAT (BB*HH*NCH)
#define MATSZ (DH*DH)
#define SZ   4160   // 64*65

__device__ float g_kpre[BL*DM];
__device__ float g_qpre[BL*DM];
__device__ float g_vpre[BL*DM];
__device__ float g_k[NMAT*MATSZ];
__device__ float g_q[NMAT*MATSZ];
__device__ float g_v[NMAT*MATSZ];
__device__ float g_gg[BH*LL];
__device__ float g_bt[BH*LL];
__device__ float g_E[NMAT];
__device__ float g_Lkk[NMAT*MATSZ];
__device__ float g_Lkv[NMAT*MATSZ];
__device__ float g_Ckk[NMAT*MATSZ];
__device__ float g_Ckv[NMAT*MATSZ];
__device__ float g_O[NMAT*MATSZ];
__device__ __nv_bfloat16 g_xhi[BL*DM];
__device__ __nv_bfloat16 g_xlo[BL*DM];
__device__ __nv_bfloat16 g_wh[4][DM*DM];
__device__ __nv_bfloat16 g_wl[4][DM*DM];

__device__ __forceinline__ uint32_t smem_u32(const void* p) {
    uint32_t a;
    asm("{ .reg .u64 t; cvta.to.shared.u64 t, %1; cvt.u32.u64 %0, t; }" : "=r"(a) : "l"(p));
    return a;
}
__device__ __forceinline__ void ldsm4(uint32_t* r, uint32_t addr) {
    asm volatile("ldmatrix.sync.aligned.m8n8.x4.shared.b16 {%0,%1,%2,%3}, [%4];"
                 : "=r"(r[0]), "=r"(r[1]), "=r"(r[2]), "=r"(r[3]) : "r"(addr));
}
__device__ __forceinline__ void mma_bf16(float* c, const uint32_t* a, const uint32_t* b) {
    asm volatile(
        "mma.sync.aligned.m16n8k16.row.col.f32.bf16.bf16.f32 "
        "{%0,%1,%2,%3}, {%4,%5,%6,%7}, {%8,%9}, {%0,%1,%2,%3};"
        : "+f"(c[0]), "+f"(c[1]), "+f"(c[2]), "+f"(c[3])
        : "r"(a[0]), "r"(a[1]), "r"(a[2]), "r"(a[3]), "r"(b[0]), "r"(b[1]));
}
__device__ __forceinline__ void cp16(uint32_t dst, const void* src) {
    asm volatile("cp.async.cg.shared.global [%0], [%1], 16;" :: "r"(dst), "l"(src) : "memory");
}
#define CP_COMMIT() asm volatile("cp.async.commit_group;" ::: "memory")
#define CP_WAIT(n)  asm volatile("cp.async.wait_group %0;" :: "n"(n) : "memory")

#define STG 40960
#define GEMM_SMEM (2*STG)
#define PC_SMEM (6*SZ*4)

__global__ __launch_bounds__(256) void split_x(const float* __restrict__ src)
{
    int i = blockIdx.x * 256 + threadIdx.x;
    for (; i < BL * DM / 4; i += gridDim.x * 256) {
        float4 a = *(const float4*)(src + (size_t)i * 4);
        __nv_bfloat16 h0 = __float2bfloat16(a.x), h1 = __float2bfloat16(a.y);
        __nv_bfloat16 h2 = __float2bfloat16(a.z), h3 = __float2bfloat16(a.w);
        __nv_bfloat16 l0 = __float2bfloat16(a.x - __bfloat162float(h0));
        __nv_bfloat16 l1 = __float2bfloat16(a.y - __bfloat162float(h1));
        __nv_bfloat16 l2 = __float2bfloat16(a.z - __bfloat162float(h2));
        __nv_bfloat16 l3 = __float2bfloat16(a.w - __bfloat162float(h3));
        __nv_bfloat162 ph0(h0, h1), ph1(h2, h3), pl0(l0, l1), pl1(l2, l3);
        *(uint2*)(g_xhi + (size_t)i * 4) = make_uint2(*(uint32_t*)&ph0, *(uint32_t*)&ph1);
        *(uint2*)(g_xlo + (size_t)i * 4) = make_uint2(*(uint32_t*)&pl0, *(uint32_t*)&pl1);
    }
}

__global__ __launch_bounds__(256) void wtsplit(
    const float* __restrict__ W0, const float* __restrict__ W1,
    const float* __restrict__ W2, const float* __restrict__ W3)
{
    __shared__ float s[32][33];
    int widx = blockIdx.z;
    const float* W = (widx == 0) ? W0 : (widx == 1) ? W1 : (widx == 2) ? W2 : W3;
    int bk = blockIdx.y << 5, bn = blockIdx.x << 5;
    int lx = threadIdx.x & 31, ly = threadIdx.x >> 5;
#pragma unroll
    for (int i = 0; i < 4; i++) {
        int r = ly + (i << 3);
        s[r][lx] = W[(size_t)(bk + r) * DM + bn + lx];
    }
    __syncthreads();
#pragma unroll
    for (int i = 0; i < 4; i++) {
        int r = ly + (i << 3);
        float v = s[lx][r];
        __nv_bfloat16 h = __float2bfloat16(v);
        __nv_bfloat16 l = __float2bfloat16(v - __bfloat162float(h));
        size_t o = (size_t)(bn + r) * DM + bk + lx;
        g_wh[widx][o] = h;
        g_wl[widx][o] = l;
    }
}

__device__ __forceinline__ void gemm_load_stage(
    uint32_t st, int nbase, int bm, int bn, int k0, int tid)
{
    const __nv_bfloat16* Bh = (const __nv_bfloat16*)g_wh + (size_t)nbase * DM;
    const __nv_bfloat16* Bl = (const __nv_bfloat16*)g_wl + (size_t)nbase * DM;
#pragma unroll
    for (int i = 0; i < 2; i++) {
        int c = tid + (i << 8);
        int row = c >> 2, seg = c & 3;
        uint32_t dst = st + row * 80 + seg * 16;
        size_t ka = (size_t)(bm + row) * DM + k0 + seg * 8;
        size_t kb = (size_t)(bn + row) * DM + k0 + seg * 8;
        cp16(dst,         g_xhi + ka);
        cp16(dst + 10240, g_xlo + ka);
        cp16(dst + 20480, Bh + kb);
        cp16(dst + 30720, Bl + kb);
    }
}

__global__ __launch_bounds__(256, 2) void gemm_mma(
    int nbase, const float* __restrict__ b0, const float* __restrict__ b1,
    const float* __restrict__ b2, float* __restrict__ Cext, int mode)
{
    extern __shared__ char smem[];
    uint32_t sb = smem_u32(smem);
    int tid = threadIdx.x;
    int bn = blockIdx.x << 7, bm = blockIdx.y << 7;
    int wid = tid >> 5, l = tid & 31;
    int wm = (wid & 3) << 5;
    int wn = (wid >> 2) << 6;

    int region = bn >> 10;
    const float* bias = mode ? b0 : (region == 0 ? b0 : region == 1 ? b1 : b2);
    float* C = mode ? Cext : (region == 0 ? g_kpre : region == 1 ? g_qpre : g_vpre);
    int bnl = mode ? bn : (bn & 1023);

    uint32_t a_off = (uint32_t)((wm + (l & 15)) * 80 + ((l >> 4) << 4));
    uint32_t b_off = (uint32_t)((wn + ((l >> 4) << 3) + (l & 7)) * 80 + (((l >> 3) & 1) << 4));

    float acc[2][8][4];
#pragma unroll
    for (int mf = 0; mf < 2; mf++)
#pragma unroll
        for (int nf = 0; nf < 8; nf++)
#pragma unroll
            for (int i = 0; i < 4; i++) acc[mf][nf][i] = 0.f;

    gemm_load_stage(sb, nbase, bm, bn, 0, tid); CP_COMMIT();

    const int NK = DM / 32;
    for (int kt = 0; kt < NK; kt++) {
        if (kt + 1 < NK) {
            gemm_load_stage(sb + ((kt + 1) & 1) * STG, nbase, bm, bn, (kt + 1) << 5, tid);
            CP_COMMIT();
            CP_WAIT(1);
        } else {
            CP_WAIT(0);
        }
        __syncthreads();

        uint32_t sA = sb + (kt & 1) * STG;
        uint32_t sAl = sA + 10240, sBh = sA + 20480, sBl = sA + 30720;
#pragma unroll
        for (int ks = 0; ks < 2; ks++) {
            uint32_t koff = ks << 5;
            uint32_t ah[2][4], al[2][4], b[8][2];
#pragma unroll
            for (int mf = 0; mf < 2; mf++) {
                ldsm4(ah[mf], sA  + a_off + mf * (16 * 80) + koff);
                ldsm4(al[mf], sAl + a_off + mf * (16 * 80) + koff);
            }
#pragma unroll
            for (int g = 0; g < 4; g++) {
                uint32_t r[4];
                ldsm4(r, sBh + b_off + g * (16 * 80) + koff);
                b[2 * g][0] = r[0]; b[2 * g][1] = r[1];
                b[2 * g + 1][0] = r[2]; b[2 * g + 1][1] = r[3];
            }
#pragma unroll
            for (int mf = 0; mf < 2; mf++)
#pragma unroll
                for (int nf = 0; nf < 8; nf++) mma_bf16(acc[mf][nf], ah[mf], b[nf]);
#pragma unroll
            for (int mf = 0; mf < 2; mf++)
#pragma unroll
                for (int nf = 0; nf < 8; nf++) mma_bf16(acc[mf][nf], al[mf], b[nf]);
#pragma unroll
            for (int g = 0; g < 4; g++) {
                uint32_t r[4];
                ldsm4(r, sBl + b_off + g * (16 * 80) + koff);
                b[2 * g][0] = r[0]; b[2 * g][1] = r[1];
                b[2 * g + 1][0] = r[2]; b[2 * g + 1][1] = r[3];
            }
#pragma unroll
            for (int mf = 0; mf < 2; mf++)
#pragma unroll
                for (int nf = 0; nf < 8; nf++) mma_bf16(acc[mf][nf], ah[mf], b[nf]);
        }
        __syncthreads();
    }

    int r4 = l >> 2, c2 = (l & 3) << 1;
#pragma unroll
    for (int mf = 0; mf < 2; mf++) {
        int row0 = bm + wm + mf * 16 + r4;
#pragma unroll
        for (int nf = 0; nf < 8; nf++) {
            int col = bnl + wn + nf * 8 + c2;
            float bb0 = bias[col], bb1 = bias[col + 1];
            float2 v0 = make_float2(acc[mf][nf][0] + bb0, acc[mf][nf][1] + bb1);
            float2 v1 = make_float2(acc[mf][nf][2] + bb0, acc[mf][nf][3] + bb1);
            *(float2*)(C + (size_t)row0 * DM + col) = v0;
            *(float2*)(C + (size_t)(row0 + 8) * DM + col) = v1;
        }
    }
}

__global__ __launch_bounds__(128) void ab_kernel(
    const float* __restrict__ x, const float* __restrict__ Wa,
    const float* __restrict__ ba, const float* __restrict__ Wb,
    const float* __restrict__ bb, const float* __restrict__ A_log,
    const float* __restrict__ dtb)
{
    __shared__ __align__(16) float xr[DM];
    __shared__ float red[128];
    int bid = blockIdx.x;
    int b = bid >> 12, l = bid & 4095;
    const float4* xs = (const float4*)(x + (size_t)bid * DM);
    float4* xr4 = (float4*)xr;
    xr4[threadIdx.x] = xs[threadIdx.x];
    xr4[threadIdx.x + 128] = xs[threadIdx.x + 128];
    __syncthreads();

    int col = threadIdx.x & 31;
    int seg = threadIdx.x >> 5;
    const float* W = (col < 16) ? (Wa + col) : (Wb + (col - 16));
    float acc = 0.f;
    int k0 = seg << 8;
#pragma unroll 8
    for (int k = 0; k < 256; k++) acc += xr[k0 + k] * W[(size_t)(k0 + k) * HH];
    red[threadIdx.x] = acc;
    __syncthreads();
    if (threadIdx.x < 32) {
        float a = red[threadIdx.x] + red[threadIdx.x + 32] +
                  red[threadIdx.x + 64] + red[threadIdx.x + 96];
        if (col < 16) {
            int h = col;
            float z = a + ba[h] + dtb[h];
            float sp = (z > 20.f) ? z : log1pf(expf(z));
            g_gg[(size_t)(b * HH + h) * LL + l] = -expf(A_log[h]) * sp;
        } else {
            int h = col - 16;
            float z = a + bb[h];
            g_bt[(size_t)(b * HH + h) * LL + l] = 1.f / (1.f + expf(-z));
        }
    }
}

__global__ __launch_bounds__(128) void conv_silu_kernel(
    const float* __restrict__ cwk, const float* __restrict__ cbk,
    const float* __restrict__ cwq, const float* __restrict__ cbq,
    const float* __restrict__ cwv, const float* __restrict__ cbv)
{
    int which = blockIdx.z;
    const float* pre = (which == 0) ? g_kpre : (which == 1) ? g_qpre : g_vpre;
    float* out = (which == 0) ? g_k : (which == 1) ? g_q : g_v;
    const float* cw = (which == 0) ? cwk : (which == 1) ? cwq : cwv;
    const float* cb = (which == 0) ? cbk : (which == 1) ? cbq : cbv;
    int do_norm = (which < 2);

    int gwarp = blockIdx.x * 4 + (threadIdx.x >> 5);
    int lane = threadIdx.x & 31;
    int h = gwarp & 15;
    int l = (gwarp >> 4) & 4095;
    int b = gwarp >> 16;
    int d0 = lane, d1 = lane + 32;
    int dm0 = h * DH + d0, dm1 = h * DH + d1;

    float a0 = cb[dm0], a1 = cb[dm1];
    const float* w0 = cw + dm0 * 4;
    const float* w1 = cw + dm1 * 4;
    size_t base = (size_t)b * LL * DM;
#pragma unroll
    for (int i = 0; i < 4; i++) {
        int li = l - 3 + i;
        if (li >= 0) {
            a0 += w0[i] * pre[base + (size_t)li * DM + dm0];
            a1 += w1[i] * pre[base + (size_t)li * DM + dm1];
        }
    }
    float s0 = a0 / (1.f + expf(-a0));
    float s1 = a1 / (1.f + expf(-a1));
    if (do_norm) {
        float ss = s0 * s0 + s1 * s1;
#pragma unroll
        for (int o = 16; o > 0; o >>= 1) ss += __shfl_xor_sync(0xffffffffu, ss, o);
        float sc = 1.f / (sqrtf(ss) + 1e-6f);
        s0 *= sc; s1 *= sc;
    }
    int n = l >> 6, t = l & 63;
    size_t ob = ((size_t)(b * HH + h) * NCH + n) * (CC * DH) + (size_t)t * DH;
    out[ob + d0] = s0;
    out[ob + d1] = s1;
}

__global__ __launch_bounds__(64) void phaseA_kernel()
{
    __shared__ float ks[4096], vs[4096];
    __shared__ float gs[64], bs[64], cs[64], wgt[64];
    int bid = blockIdx.x, t = threadIdx.x;
    size_t base = (size_t)bid * MATSZ;
    for (int i = t; i < 4096; i += 64) { ks[i] = g_k[base + i]; vs[i] = g_v[base + i]; }
    int bh = bid >> 6, n = bid & 63;
    gs[t] = g_gg[(size_t)bh * LL + n * 64 + t];
    bs[t] = g_bt[(size_t)bh * LL + n * 64 + t];
    __syncthreads();
    float c = 0.f;
    for (int j = 0; j <= t; j++) c += gs[j];
    cs[t] = c;
    __syncthreads();
    float cl = cs[63];
    wgt[t] = expf(cl - cs[t]) * bs[t];
    if (t == 0) g_E[bid] = expf(cl);
    __syncthreads();

    float akk[64], akv[64];
#pragma unroll
    for (int d = 0; d < 64; d++) { akk[d] = 0.f; akv[d] = 0.f; }
    for (int m = 0; m < 64; m++) {
        float w = wgt[m];
        float ce = w * ks[m * 64 + t];
        float cv = w * vs[m * 64 + t];
#pragma unroll
        for (int d = 0; d < 64; d++) {
            float kmd = ks[m * 64 + d];
            akk[d] += ce * kmd;
            akv[d] += cv * kmd;
        }
    }
#pragma unroll
    for (int d = 0; d < 64; d++) {
        g_Lkk[base + d * 64 + t] = akk[d];
        g_Lkv[base + d * 64 + t] = akv[d];
    }
}

__global__ __launch_bounds__(256) void scan_kernel()
{
    int bh = blockIdx.x;
    int e = blockIdx.y * 256 + threadIdx.x;
    float ckk = ((e >> 6) == (e & 63)) ? 1.f : 0.f;
    float ckv = 0.f;
    const float* EE = g_E + bh * 64;
    size_t base = (size_t)bh * 64 * MATSZ + e;
    for (int n = 0; n < 64; n++) {
        size_t o = base + (size_t)n * MATSZ;
        float E = EE[n];
        g_Ckk[o] = ckk;
        g_Ckv[o] = ckv;
        ckk = E * ckk + g_Lkk[o];
        ckv = E * ckv + g_Lkv[o];
    }
}

// ---- Phase C v2: Woodbury + Cholesky, chunk-parallel ----
// O_j = R1[j,:] + sum_{m<=j} Theta[m,j] * Xp[m,:]
__global__ __launch_bounds__(128) void phaseC_kernel()
{
    extern __shared__ float sh[];
    float* B0 = sh;            // C -> MC -> R1
    float* B1 = sh + SZ;       // I -> Minv -> G/L
    float* B2 = sh + 2 * SZ;   // KT[m][d]
    float* B3 = sh + 3 * SZ;   // QT[j][d] -> Z/Theta[m][j]
    float* B4 = sh + 4 * SZ;   // Ckv[e][t] -> P[d][m]
    float* B5 = sh + 5 * SZ;   // V[m][t] -> X -> Xp
    __shared__ float gs[64], bs[64], binv[64], Linv[64];

    int tile = blockIdx.x, tid = threadIdx.x;
    int t = tid & 63, h = tid >> 6, r0 = h << 5;
    int bh = tile >> 6, n = tile & 63;
    size_t tb = (size_t)tile * MATSZ;

#pragma unroll
    for (int i = 0; i < 32; i++) {
        int r = r0 + i;
        B0[r * 65 + t] = g_Ckk[tb + r * 64 + t];
        B1[r * 65 + t] = (r == t) ? 1.f : 0.f;
        B2[r * 65 + t] = g_k[tb + r * 64 + t];
        B3[r * 65 + t] = g_q[tb + r * 64 + t];
        B4[r * 65 + t] = g_Ckv[tb + r * 64 + t];
        B5[r * 65 + t] = g_v[tb + r * 64 + t];
    }
    if (tid < 64) {
        gs[t] = g_gg[(size_t)bh * LL + n * 64 + t];
        bs[t] = g_bt[(size_t)bh * LL + n * 64 + t];
    }
    __syncthreads();
    if (tid < 64) {
        float c = 0.f;
        for (int j = 0; j <= t; j++) c += gs[j];
        binv[t] = expf(c) / bs[t];   // 1/b_t
    }

    // GJ: B1 = inv(C). 3 barriers/pivot (reads hoisted: race-free).
    for (int p = 0; p < 64; p++) {
        float piv = B0[p * 65 + p];
        float f = (t != p) ? B0[t * 65 + p] : 0.f;
        __syncthreads();
        if (t == p) {
            float inv = 1.f / piv;
#pragma unroll
            for (int c = 0; c < 32; c++) {
                B0[p * 65 + r0 + c] *= inv;
                B1[p * 65 + r0 + c] *= inv;
            }
        }
        __syncthreads();
        if (t != p) {
#pragma unroll
            for (int c = 0; c < 32; c++) {
                B0[t * 65 + r0 + c] -= f * B0[p * 65 + r0 + c];
                B1[t * 65 + r0 + c] -= f * B1[p * 65 + r0 + c];
            }
        }
        __syncthreads();
    }

    // MC = Minv * Ckv -> B0 (C dead)
#pragma unroll 4
    for (int i = 0; i < 32; i++) {
        int d = r0 + i;
        float a = 0.f;
        for (int e = 0; e < 64; e++) a += B1[d * 65 + e] * B4[e * 65 + t];
        B0[d * 65 + t] = a;
    }
    __syncthreads();

    // P = Minv*KT -> B4 (Ckv dead); X = V - K*MC (in-place B5); R1 = Q*MC (regs)
    float r1[32];
#pragma unroll 4
    for (int i = 0; i < 32; i++) {
        int d = r0 + i;
        float a = 0.f;
        for (int e = 0; e < 64; e++) a += B1[d * 65 + e] * B2[t * 65 + e];
        B4[d * 65 + t] = a;   // P[d][m=t]
    }
#pragma unroll 4
    for (int i = 0; i < 32; i++) {
        int m = r0 + i;
        float a = 0.f, b = 0.f;
        for (int d = 0; d < 64; d++) {
            float mc = B0[d * 65 + t];
            a += B2[m * 65 + d] * mc;
            b += B3[m * 65 + d] * mc;
        }
        B5[m * 65 + t] -= a;  // X
        r1[i] = b;            // R1[j=m][t]
    }
    __syncthreads();
#pragma unroll
    for (int i = 0; i < 32; i++) B0[(r0 + i) * 65 + t] = r1[i];  // R1 -> B0 (MC dead)

    // G = diag(1/b) + K*P -> B1 (Minv dead); Z masked = Q*P (regs) -> B3
    float zz[32];
#pragma unroll 4
    for (int i = 0; i < 32; i++) {
        int m = r0 + i;
        float a = 0.f;
        for (int d = 0; d < 64; d++) a += B2[m * 65 + d] * B4[d * 65 + t];
        B1[m * 65 + t] = a + ((m == t) ? binv[t] : 0.f);
    }
#pragma unroll 4
    for (int i = 0; i < 32; i++) {
        int m = r0 + i;
        float a = 0.f;
        if (m <= t) {
            for (int d = 0; d < 64; d++) a += B3[t * 65 + d] * B4[d * 65 + m];
        }
        zz[i] = a;
    }
    __syncthreads();
#pragma unroll
    for (int i = 0; i < 32; i++) B3[(r0 + i) * 65 + t] = zz[i];  // Z[m][j=t]
    __syncthreads();

    // Cholesky of G in B1 (lower), Linv[p]=1/L[p][p]
    for (int p = 0; p < 64; p++) {
        float tmp = 0.f;
        if (h == 0 && t >= p) {
            tmp = B1[t * 65 + p];
            for (int i = 0; i < p; i++) tmp -= B1[t * 65 + i] * B1[p * 65 + i];
            if (t == p) {
                float lpp = sqrtf(fmaxf(tmp, 1e-30f));
                B1[p * 65 + p] = lpp;
                Linv[p] = 1.f / lpp;
            }
        }
        __syncthreads();
        if (h == 0 && t > p) B1[t * 65 + p] = tmp * Linv[p];
        __syncthreads();
    }

    // forward substitutions (barrier-free): h==0: Theta col t (m<=t); h==1: Xp col t
    if (h == 0) {
        for (int m = 0; m <= t; m++) {
            float s = B3[m * 65 + t];
            for (int i = 0; i < m; i++) s -= B1[m * 65 + i] * B3[i * 65 + t];
            B3[m * 65 + t] = s * Linv[m];
        }
    } else {
        for (int m = 0; m < 64; m++) {
            float s = B5[m * 65 + t];
            for (int i = 0; i < m; i++) s -= B1[m * 65 + i] * B5[i * 65 + t];
            B5[m * 65 + t] = s * Linv[m];
        }
    }
    __syncthreads();

    // O[j][t] = R1[j][t] + sum_{m<=j} Theta[m][j]*Xp[m][t]
#pragma unroll 4
    for (int i = 0; i < 32; i++) {
        int j = r0 + i;
        float o = B0[j * 65 + t];
        for (int m = 0; m <= j; m++) o += B3[m * 65 + j] * B5[m * 65 + t];
        g_O[tb + j * 64 + t] = o;
    }
}

__global__ __launch_bounds__(128) void rms_split_kernel(const float* __restrict__ nw)
{
    int gwarp = blockIdx.x * 4 + (threadIdx.x >> 5);
    int lane = threadIdx.x & 31;
    int h = gwarp & 15;
    int l = (gwarp >> 4) & 4095;
    int b = gwarp >> 16;
    int n = l >> 6, c = l & 63;
    size_t rb = (((size_t)(b * HH + h) * NCH + n) * CC + c) * DH;
    float o0 = g_O[rb + lane], o1 = g_O[rb + lane + 32];
    float ss = o0 * o0 + o1 * o1;
#pragma unroll
    for (int o = 16; o > 0; o >>= 1) ss += __shfl_xor_sync(0xffffffffu, ss, o);
    float sc = rsqrtf(ss * (1.f / 64.f) + 1e-6f);
    float v0 = o0 * sc * nw[lane];
    float v1 = o1 * sc * nw[lane + 32];
    size_t ob = (size_t)(b * LL + l) * DM + h * DH;
    __nv_bfloat16 h0 = __float2bfloat16(v0);
    __nv_bfloat16 h1 = __float2bfloat16(v1);
    g_xhi[ob + lane] = h0;
    g_xhi[ob + lane + 32] = h1;
    g_xlo[ob + lane] = __float2bfloat16(v0 - __bfloat162float(h0));
    g_xlo[ob + lane + 32] = __float2bfloat16(v1 - __bfloat162float(h1));
}

extern "C" void kernel_launch(void* const* d_in, const int* in_sizes, int n_in,
                              void* d_out, int out_size)
{
    const float* x   = (const float*)d_in[0];
    const float* Wk  = (const float*)d_in[1];  const float* bk  = (const float*)d_in[2];
    const float* Wq  = (const float*)d_in[3];  const float* bq  = (const float*)d_in[4];
    const float* Wv  = (const float*)d_in[5];  const float* bv  = (const float*)d_in[6];
    const float* Wa  = (const float*)d_in[7];  const float* ba  = (const float*)d_in[8];
    const float* Wbt = (const float*)d_in[9];  const float* bbt = (const float*)d_in[10];
    const float* Wo  = (const float*)d_in[11]; const float* bo  = (const float*)d_in[12];
    const float* A_log = (const float*)d_in[13];
    const float* dtb = (const float*)d_in[14];
    const float* cwk = (const float*)d_in[15]; const float* cbk = (const float*)d_in[16];
    const float* cwq = (const float*)d_in[17]; const float* cbq = (const float*)d_in[18];
    const float* cwv = (const float*)d_in[19]; const float* cbv = (const float*)d_in[20];
    const float* nw  = (const float*)d_in[21];
    float* out = (float*)d_out;

    cudaFuncSetAttribute(gemm_mma, cudaFuncAttributeMaxDynamicSharedMemorySize, GEMM_SMEM);
    cudaFuncSetAttribute(phaseC_kernel, cudaFuncAttributeMaxDynamicSharedMemorySize, PC_SMEM);

    wtsplit<<<dim3(32, 32, 4), 256>>>(Wk, Wq, Wv, Wo);
    split_x<<<4096, 256>>>(x);
    ab_kernel<<<BL, 128>>>(x, Wa, ba, Wbt, bbt, A_log, dtb);
    gemm_mma<<<dim3(3 * DM / 128, BL / 128), 256, GEMM_SMEM>>>(0, bk, bq, bv, nullptr, 0);
    conv_silu_kernel<<<dim3(BB * LL * HH / 4, 1, 3), 128>>>(cwk, cbk, cwq, cbq, cwv, cbv);
    phaseA_kernel<<<NMAT, 64>>>();
    scan_kernel<<<dim3(BH, 16), 256>>>();
    phaseC_kernel<<<NMAT, 128, PC_SMEM>>>();
    rms_split_kernel<<<BB * LL * HH / 4, 128>>>(nw);
    gemm_mma<<<dim3(DM / 128, BL / 128), 256, GEMM_SMEM>>>(3 * DM, bo, nullptr, nullptr, out, 1);
}